// round 1
// baseline (speedup 1.0000x reference)
#include <cuda_runtime.h>
#include <math.h>

#define BB 4
#define CC 64
#define NN 4096
#define TQ 64
#define TK 64
#define WSTRIDE 68
#define PSTRIDE 68

// Scratch (allocation-free rule: __device__ globals)
__device__ float g_q[BB * CC * NN];   // (b, c, n)  pre-scaled by 1/N, bias folded
__device__ float g_k[BB * CC * NN];   // (b, c, n)
__device__ float g_vT[BB * NN * CC];  // (b, n, c)  token-major for P@V

// ---------------------------------------------------------------------------
// Kernel 1: fused QKV projection (1x1 conv == per-token linear over channels)
// grid (N/64, B), 256 threads. Each block: 64-token tile, all 3 projections.
// ---------------------------------------------------------------------------
__global__ void __launch_bounds__(256) proj_kernel(
    const float* __restrict__ x,
    const float* __restrict__ wq, const float* __restrict__ bq,
    const float* __restrict__ wk, const float* __restrict__ bk,
    const float* __restrict__ wv, const float* __restrict__ bv)
{
    extern __shared__ float sm[];
    float* Xs = sm;                 // [C][64]      c-major
    float* Ws = sm + CC * 64;       // [3][C][WSTRIDE]  (c-major, transposed weights)

    const int b  = blockIdx.y;
    const int n0 = blockIdx.x * 64;
    const int tid = threadIdx.x;

    // Load X tile: row = channel, 64 contiguous tokens (coalesced)
    {
        int row = tid >> 2;
        int col = (tid & 3) * 16;
        const float* src = x + ((size_t)(b * CC + row) * NN + n0 + col);
        float* dst = Xs + row * 64 + col;
        #pragma unroll
        for (int k = 0; k < 16; k += 4)
            *(float4*)(dst + k) = *(const float4*)(src + k);
    }
    // Load weights transposed: Ws[m][c][o] = w[o][c]
    {
        const float* wsrc[3] = {wq, wk, wv};
        #pragma unroll
        for (int m = 0; m < 3; m++) {
            const float* w = wsrc[m];
            for (int idx = tid; idx < CC * CC; idx += 256) {
                int o = idx >> 6, c = idx & 63;
                Ws[(m * CC + c) * WSTRIDE + o] = w[idx];
            }
        }
    }
    __syncthreads();

    const int ti = tid >> 4, tj = tid & 15;
    const int o0 = ti * 4, nn0 = tj * 4;

    float acc[3][4][4];
    #pragma unroll
    for (int m = 0; m < 3; m++)
        #pragma unroll
        for (int i = 0; i < 4; i++)
            #pragma unroll
            for (int j = 0; j < 4; j++) acc[m][i][j] = 0.f;

    #pragma unroll 4
    for (int c = 0; c < CC; c++) {
        float4 x4 = *(float4*)(Xs + c * 64 + nn0);
        float xv[4] = {x4.x, x4.y, x4.z, x4.w};
        #pragma unroll
        for (int m = 0; m < 3; m++) {
            float4 w4 = *(float4*)(Ws + (m * CC + c) * WSTRIDE + o0);
            float wv_[4] = {w4.x, w4.y, w4.z, w4.w};
            #pragma unroll
            for (int oo = 0; oo < 4; oo++)
                #pragma unroll
                for (int nn = 0; nn < 4; nn++)
                    acc[m][oo][nn] += wv_[oo] * xv[nn];
        }
    }

    const float invN = 1.0f / (float)NN;
    float bqv[4], bkv[4], bvv[4];
    #pragma unroll
    for (int oo = 0; oo < 4; oo++) {
        bqv[oo] = bq[o0 + oo];
        bkv[oo] = bk[o0 + oo];
        bvv[oo] = bv[o0 + oo];
    }
    // Q (scaled by 1/N) and K, channel-major, coalesced float4 stores
    #pragma unroll
    for (int oo = 0; oo < 4; oo++) {
        int o = o0 + oo;
        size_t base = (size_t)(b * CC + o) * NN + n0 + nn0;
        float4 qo = make_float4((acc[0][oo][0] + bqv[oo]) * invN,
                                (acc[0][oo][1] + bqv[oo]) * invN,
                                (acc[0][oo][2] + bqv[oo]) * invN,
                                (acc[0][oo][3] + bqv[oo]) * invN);
        float4 ko = make_float4(acc[1][oo][0] + bkv[oo],
                                acc[1][oo][1] + bkv[oo],
                                acc[1][oo][2] + bkv[oo],
                                acc[1][oo][3] + bkv[oo]);
        *(float4*)(g_q + base) = qo;
        *(float4*)(g_k + base) = ko;
    }
    // V token-major
    #pragma unroll
    for (int nn = 0; nn < 4; nn++) {
        float4 vo = make_float4(acc[2][0][nn] + bvv[0],
                                acc[2][1][nn] + bvv[1],
                                acc[2][2][nn] + bvv[2],
                                acc[2][3][nn] + bvv[3]);
        *(float4*)(g_vT + (size_t)(b * NN + n0 + nn0 + nn) * CC + o0) = vo;
    }
}

// ---------------------------------------------------------------------------
// Kernel 2: flash attention. grid (N/TQ, B), 256 threads = 16x16 thread grid,
// 4x4 register micro-tiles for S and O. Online softmax via 16-lane shfl.
// ---------------------------------------------------------------------------
__global__ void __launch_bounds__(256) attn_kernel(float* __restrict__ out)
{
    extern __shared__ float sm[];
    float* Qs = sm;                  // [C][TQ]  c-major
    float* Ks = Qs + CC * TQ;        // [C][TK]  c-major
    float* Vs = Ks + CC * TK;        // [TK][C]  token-major
    float* Ps = Vs + TK * CC;        // [TQ][PSTRIDE]

    const int b  = blockIdx.y;
    const int q0 = blockIdx.x * TQ;
    const int tid = threadIdx.x;
    const int ti = tid >> 4, tj = tid & 15;
    const int i0 = ti * 4;           // query rows owned
    const int j0s = tj * 4;          // key cols owned (S phase)
    const int c0 = tj * 4;           // channels owned (O phase)

    // Load Q tile (already pre-scaled by 1/N)
    {
        int row = tid >> 2;
        int col = (tid & 3) * 16;
        const float* src = g_q + ((size_t)(b * CC + row) * NN + q0 + col);
        float* dst = Qs + row * TQ + col;
        #pragma unroll
        for (int k = 0; k < 16; k += 4)
            *(float4*)(dst + k) = *(const float4*)(src + k);
    }

    float O[4][4];
    #pragma unroll
    for (int r = 0; r < 4; r++)
        #pragma unroll
        for (int cc = 0; cc < 4; cc++) O[r][cc] = 0.f;
    float mrow[4], lrow[4];
    #pragma unroll
    for (int r = 0; r < 4; r++) { mrow[r] = -INFINITY; lrow[r] = 0.f; }

    for (int kt = 0; kt < NN / TK; kt++) {
        const int j0 = kt * TK;
        __syncthreads();
        // Load K (c-major) and V (token-major) tiles, coalesced
        {
            int row = tid >> 2;
            int col = (tid & 3) * 16;
            const float* ksrc = g_k + ((size_t)(b * CC + row) * NN + j0 + col);
            float* kdst = Ks + row * TK + col;
            const float* vsrc = g_vT + ((size_t)(b * NN + j0 + row) * CC + col);
            float* vdst = Vs + row * CC + col;
            #pragma unroll
            for (int k = 0; k < 16; k += 4) {
                *(float4*)(kdst + k) = *(const float4*)(ksrc + k);
                *(float4*)(vdst + k) = *(const float4*)(vsrc + k);
            }
        }
        __syncthreads();

        // S[4][4] = Q_tile^T K_tile  (already includes 1/N via Q scaling)
        float S[4][4];
        #pragma unroll
        for (int r = 0; r < 4; r++)
            #pragma unroll
            for (int jj = 0; jj < 4; jj++) S[r][jj] = 0.f;
        #pragma unroll 8
        for (int c = 0; c < CC; c++) {
            float4 q4 = *(float4*)(Qs + c * TQ + i0);
            float4 k4 = *(float4*)(Ks + c * TK + j0s);
            float qv[4] = {q4.x, q4.y, q4.z, q4.w};
            float kv[4] = {k4.x, k4.y, k4.z, k4.w};
            #pragma unroll
            for (int r = 0; r < 4; r++)
                #pragma unroll
                for (int jj = 0; jj < 4; jj++)
                    S[r][jj] += qv[r] * kv[jj];
        }

        // Online softmax per owned row
        #pragma unroll
        for (int r = 0; r < 4; r++) {
            float mx = fmaxf(fmaxf(S[r][0], S[r][1]), fmaxf(S[r][2], S[r][3]));
            #pragma unroll
            for (int off = 8; off > 0; off >>= 1)
                mx = fmaxf(mx, __shfl_xor_sync(0xffffffffu, mx, off));
            float mn = fmaxf(mrow[r], mx);
            float corr = __expf(mrow[r] - mn);
            float p0 = __expf(S[r][0] - mn);
            float p1 = __expf(S[r][1] - mn);
            float p2 = __expf(S[r][2] - mn);
            float p3 = __expf(S[r][3] - mn);
            float s = (p0 + p1) + (p2 + p3);
            #pragma unroll
            for (int off = 8; off > 0; off >>= 1)
                s += __shfl_xor_sync(0xffffffffu, s, off);
            lrow[r] = lrow[r] * corr + s;
            mrow[r] = mn;
            #pragma unroll
            for (int cc = 0; cc < 4; cc++) O[r][cc] *= corr;
            *(float4*)(Ps + (i0 + r) * PSTRIDE + j0s) = make_float4(p0, p1, p2, p3);
        }
        __syncthreads();

        // O += P @ V
        #pragma unroll 8
        for (int j = 0; j < TK; j++) {
            float4 v4 = *(float4*)(Vs + j * CC + c0);
            #pragma unroll
            for (int r = 0; r < 4; r++) {
                float pr = Ps[(i0 + r) * PSTRIDE + j];
                O[r][0] += pr * v4.x;
                O[r][1] += pr * v4.y;
                O[r][2] += pr * v4.z;
                O[r][3] += pr * v4.w;
            }
        }
    }

    // Epilogue: out[b][c][n] = O / l
    #pragma unroll
    for (int r = 0; r < 4; r++) {
        float inv = 1.0f / lrow[r];
        int i = q0 + i0 + r;
        #pragma unroll
        for (int cc = 0; cc < 4; cc++)
            out[(size_t)(b * CC + c0 + cc) * NN + i] = O[r][cc] * inv;
    }
}

// ---------------------------------------------------------------------------
extern "C" void kernel_launch(void* const* d_in, const int* in_sizes, int n_in,
                              void* d_out, int out_size)
{
    const float* x  = (const float*)d_in[0];
    const float* wq = (const float*)d_in[1];
    const float* bq = (const float*)d_in[2];
    const float* wk = (const float*)d_in[3];
    const float* bk = (const float*)d_in[4];
    const float* wv = (const float*)d_in[5];
    const float* bv = (const float*)d_in[6];
    float* out = (float*)d_out;

    const int smem_proj = (CC * 64 + 3 * CC * WSTRIDE) * sizeof(float);
    const int smem_attn = (CC * TQ + CC * TK + TK * CC + TQ * PSTRIDE) * sizeof(float);
    cudaFuncSetAttribute(proj_kernel, cudaFuncAttributeMaxDynamicSharedMemorySize, smem_proj);
    cudaFuncSetAttribute(attn_kernel, cudaFuncAttributeMaxDynamicSharedMemorySize, smem_attn);

    dim3 gp(NN / 64, BB);
    proj_kernel<<<gp, 256, smem_proj>>>(x, wq, bq, wk, bk, wv, bv);
    dim3 ga(NN / TQ, BB);
    attn_kernel<<<ga, 256, smem_attn>>>(out);
}

// round 3
// speedup vs baseline: 3.4807x; 3.4807x over previous
#include <cuda_runtime.h>
#include <math.h>
#include <stdint.h>

#define BB 4
#define CC 64
#define NN 4096
#define TQa 128
#define TKa 64
#define WSTRIDE 68

// Scratch (__device__ globals, allocation-free rule)
__device__ float g_q[BB * NN * CC];   // (b, n, c) token-major, tf32, pre-scaled 1/N
__device__ float g_k[BB * NN * CC];   // (b, n, c) token-major, tf32
__device__ float g_v[BB * CC * NN];   // (b, c, n) channel-major, tf32

// ---------------------------------------------------------------------------
__device__ __forceinline__ float to_tf32(float x) {
    uint32_t u;
    asm("cvt.rna.tf32.f32 %0, %1;" : "=r"(u) : "f"(x));
    return __uint_as_float(u);
}

__device__ __forceinline__ void mma8(float* d, uint32_t a0, uint32_t a1,
                                     uint32_t a2, uint32_t a3,
                                     uint32_t b0, uint32_t b1) {
    asm volatile(
        "mma.sync.aligned.m16n8k8.row.col.f32.tf32.tf32.f32 "
        "{%0,%1,%2,%3}, {%4,%5,%6,%7}, {%8,%9}, {%0,%1,%2,%3};"
        : "+f"(d[0]), "+f"(d[1]), "+f"(d[2]), "+f"(d[3])
        : "r"(a0), "r"(a1), "r"(a2), "r"(a3), "r"(b0), "r"(b1));
}

// ---------------------------------------------------------------------------
// Kernel 1: fused QKV projection (unchanged math; outputs rounded to tf32)
// ---------------------------------------------------------------------------
__global__ void __launch_bounds__(256) proj_kernel(
    const float* __restrict__ x,
    const float* __restrict__ wq, const float* __restrict__ bq,
    const float* __restrict__ wk, const float* __restrict__ bk,
    const float* __restrict__ wv, const float* __restrict__ bv)
{
    extern __shared__ float sm[];
    float* Xs = sm;               // [C][64]
    float* Ws = sm + CC * 64;     // [3][C][WSTRIDE]

    const int b  = blockIdx.y;
    const int n0 = blockIdx.x * 64;
    const int tid = threadIdx.x;

    {
        int row = tid >> 2;
        int col = (tid & 3) * 16;
        const float* src = x + ((size_t)(b * CC + row) * NN + n0 + col);
        float* dst = Xs + row * 64 + col;
        #pragma unroll
        for (int k = 0; k < 16; k += 4)
            *(float4*)(dst + k) = *(const float4*)(src + k);
    }
    {
        const float* wsrc[3] = {wq, wk, wv};
        #pragma unroll
        for (int m = 0; m < 3; m++) {
            const float* w = wsrc[m];
            for (int idx = tid; idx < CC * CC; idx += 256) {
                int o = idx >> 6, c = idx & 63;
                Ws[(m * CC + c) * WSTRIDE + o] = w[idx];
            }
        }
    }
    __syncthreads();

    const int ti = tid >> 4, tj = tid & 15;
    const int o0 = ti * 4, nn0 = tj * 4;

    float acc[3][4][4];
    #pragma unroll
    for (int m = 0; m < 3; m++)
        #pragma unroll
        for (int i = 0; i < 4; i++)
            #pragma unroll
            for (int j = 0; j < 4; j++) acc[m][i][j] = 0.f;

    #pragma unroll 4
    for (int c = 0; c < CC; c++) {
        float4 x4 = *(float4*)(Xs + c * 64 + nn0);
        float xv[4] = {x4.x, x4.y, x4.z, x4.w};
        #pragma unroll
        for (int m = 0; m < 3; m++) {
            float4 w4 = *(float4*)(Ws + (m * CC + c) * WSTRIDE + o0);
            float wv_[4] = {w4.x, w4.y, w4.z, w4.w};
            #pragma unroll
            for (int oo = 0; oo < 4; oo++)
                #pragma unroll
                for (int nn = 0; nn < 4; nn++)
                    acc[m][oo][nn] += wv_[oo] * xv[nn];
        }
    }

    const float invN = 1.0f / (float)NN;
    float bqv[4], bkv[4], bvv[4];
    #pragma unroll
    for (int oo = 0; oo < 4; oo++) {
        bqv[oo] = bq[o0 + oo];
        bkv[oo] = bk[o0 + oo];
        bvv[oo] = bv[o0 + oo];
    }
    // Q (scaled, tf32) and K (tf32) token-major (n, c)
    #pragma unroll
    for (int nn = 0; nn < 4; nn++) {
        int token = n0 + nn0 + nn;
        float4 qo = make_float4(to_tf32((acc[0][0][nn] + bqv[0]) * invN),
                                to_tf32((acc[0][1][nn] + bqv[1]) * invN),
                                to_tf32((acc[0][2][nn] + bqv[2]) * invN),
                                to_tf32((acc[0][3][nn] + bqv[3]) * invN));
        float4 ko = make_float4(to_tf32(acc[1][0][nn] + bkv[0]),
                                to_tf32(acc[1][1][nn] + bkv[1]),
                                to_tf32(acc[1][2][nn] + bkv[2]),
                                to_tf32(acc[1][3][nn] + bkv[3]));
        *(float4*)(g_q + (size_t)(b * NN + token) * CC + o0) = qo;
        *(float4*)(g_k + (size_t)(b * NN + token) * CC + o0) = ko;
    }
    // V (tf32) channel-major (c, n)
    #pragma unroll
    for (int oo = 0; oo < 4; oo++) {
        float4 vo = make_float4(to_tf32(acc[2][oo][0] + bvv[oo]),
                                to_tf32(acc[2][oo][1] + bvv[oo]),
                                to_tf32(acc[2][oo][2] + bvv[oo]),
                                to_tf32(acc[2][oo][3] + bvv[oo]));
        *(float4*)(g_v + (size_t)(b * CC + o0 + oo) * NN + n0 + nn0) = vo;
    }
}

// ---------------------------------------------------------------------------
// Kernel 2: mma.sync tf32 flash attention.
// 128 threads = 4 warps; warp owns 32 query rows (2 m16 tiles). TK=64 tiles.
// SMEM (floats): Qp[8192] | Kp[4112] | Vp[4112] | Ps[8704]
// Fragment-packed K/V: float4 slot ((s2*8+t)*32+lam), +s2 skew (bank fix).
// ---------------------------------------------------------------------------
__global__ void __launch_bounds__(128, 1) attn_mma_kernel(float* __restrict__ out)
{
    extern __shared__ float sm[];
    float* Qp = sm;                       // 8192
    float* Kp = sm + 8192;                // 4112
    float* Vp = sm + 8192 + 4112;         // 4112
    float* Ps = sm + 8192 + 4112 + 4112;  // 8704 (4 warps x 32 x 68)

    const int b  = blockIdx.y;
    const int q0 = blockIdx.x * TQa;
    const int tid = threadIdx.x, w = tid >> 5, lam = tid & 31;
    const int g = lam >> 2, tau = lam & 3;

    // ---- pack Q A-fragments once: frag (m,s) -> float4 {a0,a1,a2,a3} ----
    {
        const float* qb = g_q + (size_t)(b * NN + q0 + w * 32) * CC;
        #pragma unroll
        for (int m = 0; m < 2; m++)
            #pragma unroll
            for (int s = 0; s < 8; s++) {
                int ra = m * 16 + g, c = tau + 8 * s;
                float4 f;
                f.x = qb[ra * CC + c];
                f.y = qb[(ra + 8) * CC + c];
                f.z = qb[ra * CC + c + 4];
                f.w = qb[(ra + 8) * CC + c + 4];
                *(float4*)(Qp + w * 2048 + ((m * 8 + s) * 32 + lam) * 4) = f;
            }
    }

    float of[2][8][4];
    #pragma unroll
    for (int m = 0; m < 2; m++)
        #pragma unroll
        for (int t = 0; t < 8; t++)
            #pragma unroll
            for (int c = 0; c < 4; c++) of[m][t][c] = 0.f;
    float lA[2] = {0.f, 0.f};   // rows g+16m
    float lB[2] = {0.f, 0.f};   // rows g+8+16m

    const float* kbase = g_k + (size_t)b * NN * CC;
    const float* vbase = g_v + (size_t)b * CC * NN;
    float* Pw = Ps + w * 2176;

    for (int kt = 0; kt < NN / TKa; kt++) {
        const int j0 = kt * TKa;
        __syncthreads();  // prev tile's fragment reads complete

        // ---- fill packed K and V tiles ----
        #pragma unroll
        for (int r = 0; r < 8; r++) {
            int idx4 = tid + 128 * r;
            {   // K: token j, channels c4..c4+3 (token-major source)
                int j = idx4 >> 4, c4 = (idx4 & 15) * 4;
                float4 v = *(const float4*)(kbase + (size_t)(j0 + j) * CC + c4);
                int s2 = c4 >> 4, comp = (c4 >> 2) & 3, t = j >> 3;
                int base = ((s2 * 8 + t) * 32 + (j & 7) * 4) * 4 + comp + s2 * 4;
                Kp[base + 0]  = v.x; Kp[base + 4]  = v.y;
                Kp[base + 8]  = v.z; Kp[base + 12] = v.w;
            }
            {   // V: channel c, tokens j4..j4+3 (channel-major source)
                int c = idx4 >> 4, j4 = (idx4 & 15) * 4;
                float4 v = *(const float4*)(vbase + (size_t)c * NN + j0 + j4);
                int s2 = j4 >> 4, comp = (j4 >> 2) & 3, t = c >> 3;
                int base = ((s2 * 8 + t) * 32 + 4 * (c & 7)) * 4 + comp + s2 * 4;
                Vp[base + 0]  = v.x; Vp[base + 4]  = v.y;
                Vp[base + 8]  = v.z; Vp[base + 12] = v.w;
            }
        }
        __syncthreads();

        // ---- MMA1: S = Q K^T ----
        float sf[2][8][4];
        #pragma unroll
        for (int m = 0; m < 2; m++)
            #pragma unroll
            for (int t = 0; t < 8; t++)
                #pragma unroll
                for (int c = 0; c < 4; c++) sf[m][t][c] = 0.f;

        #pragma unroll
        for (int s2 = 0; s2 < 4; s2++) {
            uint4 qa0 = *(uint4*)(Qp + w * 2048 + ((0 + 2 * s2)     * 32 + lam) * 4);
            uint4 qa1 = *(uint4*)(Qp + w * 2048 + ((0 + 2 * s2 + 1) * 32 + lam) * 4);
            uint4 qb0 = *(uint4*)(Qp + w * 2048 + ((8 + 2 * s2)     * 32 + lam) * 4);
            uint4 qb1 = *(uint4*)(Qp + w * 2048 + ((8 + 2 * s2 + 1) * 32 + lam) * 4);
            #pragma unroll
            for (int t = 0; t < 8; t++) {
                uint4 kb = *(uint4*)(Kp + ((s2 * 8 + t) * 32 + lam) * 4 + s2 * 4);
                mma8(sf[0][t], qa0.x, qa0.y, qa0.z, qa0.w, kb.x, kb.y);
                mma8(sf[0][t], qa1.x, qa1.y, qa1.z, qa1.w, kb.z, kb.w);
                mma8(sf[1][t], qb0.x, qb0.y, qb0.z, qb0.w, kb.x, kb.y);
                mma8(sf[1][t], qb1.x, qb1.y, qb1.z, qb1.w, kb.z, kb.w);
            }
        }

        // ---- softmax (no max needed: |S| << 1); P -> SMEM (tf32) ----
        float rs[2][2] = {{0.f, 0.f}, {0.f, 0.f}};
        #pragma unroll
        for (int m = 0; m < 2; m++)
            #pragma unroll
            for (int t = 0; t < 8; t++) {
                float e0 = __expf(sf[m][t][0]);
                float e1 = __expf(sf[m][t][1]);
                float e2 = __expf(sf[m][t][2]);
                float e3 = __expf(sf[m][t][3]);
                rs[m][0] += e0 + e1;
                rs[m][1] += e2 + e3;
                int row = m * 16 + g, col = 8 * t + 2 * tau;
                float2 p01 = make_float2(to_tf32(e0), to_tf32(e1));
                float2 p23 = make_float2(to_tf32(e2), to_tf32(e3));
                *(float2*)(Pw + row * 68 + col)       = p01;
                *(float2*)(Pw + (row + 8) * 68 + col) = p23;
            }
        #pragma unroll
        for (int m = 0; m < 2; m++) {
            float a = rs[m][0], bsum = rs[m][1];
            a += __shfl_xor_sync(0xffffffffu, a, 1);
            a += __shfl_xor_sync(0xffffffffu, a, 2);
            bsum += __shfl_xor_sync(0xffffffffu, bsum, 1);
            bsum += __shfl_xor_sync(0xffffffffu, bsum, 2);
            lA[m] += a;
            lB[m] += bsum;
        }
        __syncwarp();

        // ---- MMA2: O += P V ----
        #pragma unroll
        for (int s2 = 0; s2 < 4; s2++) {
            uint32_t pa[2][2][4];
            #pragma unroll
            for (int m = 0; m < 2; m++)
                #pragma unroll
                for (int h = 0; h < 2; h++) {
                    int s = 2 * s2 + h, colb = tau + 8 * s, row = m * 16 + g;
                    pa[m][h][0] = __float_as_uint(Pw[row * 68 + colb]);
                    pa[m][h][1] = __float_as_uint(Pw[(row + 8) * 68 + colb]);
                    pa[m][h][2] = __float_as_uint(Pw[row * 68 + colb + 4]);
                    pa[m][h][3] = __float_as_uint(Pw[(row + 8) * 68 + colb + 4]);
                }
            #pragma unroll
            for (int t = 0; t < 8; t++) {
                uint4 vb = *(uint4*)(Vp + ((s2 * 8 + t) * 32 + lam) * 4 + s2 * 4);
                mma8(of[0][t], pa[0][0][0], pa[0][0][1], pa[0][0][2], pa[0][0][3], vb.x, vb.y);
                mma8(of[0][t], pa[0][1][0], pa[0][1][1], pa[0][1][2], pa[0][1][3], vb.z, vb.w);
                mma8(of[1][t], pa[1][0][0], pa[1][0][1], pa[1][0][2], pa[1][0][3], vb.x, vb.y);
                mma8(of[1][t], pa[1][1][0], pa[1][1][1], pa[1][1][2], pa[1][1][3], vb.z, vb.w);
            }
        }
    }

    // ---- epilogue: divide by row sums, write (b, c, n) ----
    float invA[2], invB[2];
    #pragma unroll
    for (int m = 0; m < 2; m++) { invA[m] = 1.f / lA[m]; invB[m] = 1.f / lB[m]; }
    #pragma unroll
    for (int m = 0; m < 2; m++)
        #pragma unroll
        for (int t = 0; t < 8; t++) {
            int rowa = q0 + w * 32 + m * 16 + g;
            int col = 8 * t + 2 * tau;
            out[(size_t)(b * CC + col)     * NN + rowa]     = of[m][t][0] * invA[m];
            out[(size_t)(b * CC + col + 1) * NN + rowa]     = of[m][t][1] * invA[m];
            out[(size_t)(b * CC + col)     * NN + rowa + 8] = of[m][t][2] * invB[m];
            out[(size_t)(b * CC + col + 1) * NN + rowa + 8] = of[m][t][3] * invB[m];
        }
}

// ---------------------------------------------------------------------------
extern "C" void kernel_launch(void* const* d_in, const int* in_sizes, int n_in,
                              void* d_out, int out_size)
{
    const float* x  = (const float*)d_in[0];
    const float* wq = (const float*)d_in[1];
    const float* bq = (const float*)d_in[2];
    const float* wk = (const float*)d_in[3];
    const float* bk = (const float*)d_in[4];
    const float* wv = (const float*)d_in[5];
    const float* bv = (const float*)d_in[6];
    float* out = (float*)d_out;

    const int smem_proj = (CC * 64 + 3 * CC * WSTRIDE) * sizeof(float);
    const int smem_attn = (8192 + 4112 + 4112 + 8704) * sizeof(float);  // 100480 B
    cudaFuncSetAttribute(proj_kernel, cudaFuncAttributeMaxDynamicSharedMemorySize, smem_proj);
    cudaFuncSetAttribute(attn_mma_kernel, cudaFuncAttributeMaxDynamicSharedMemorySize, smem_attn);

    dim3 gp(NN / 64, BB);
    proj_kernel<<<gp, 256, smem_proj>>>(x, wq, bq, wk, bk, wv, bv);
    dim3 ga(NN / TQa, BB);
    attn_mma_kernel<<<ga, 128, smem_attn>>>(out);
}